// round 4
// baseline (speedup 1.0000x reference)
#include <cuda_runtime.h>

// Problem constants
#define BB 2
#define FF 512
#define HH 192
#define WW 192
#define TT 8
#define HW (HH * WW)

#define TILEX 32
#define TILEY 4
#define NTHREADS 256
#define NWARPS 8
#define NPIX (TILEX * TILEY)   // 128 pixels/block, 2 threads each
#define MAXT 96                // texture staging capacity (typical survivors ~22)

__device__ __forceinline__ void cp_async16(void* dst_smem, const void* src_gmem) {
    unsigned saddr = (unsigned)__cvta_generic_to_shared(dst_smem);
    asm volatile("cp.async.cg.shared.global [%0], [%1], 16;\n"
                 :: "r"(saddr), "l"(src_gmem) : "memory");
}

__global__ __launch_bounds__(NTHREADS)
void raster_kernel(const float* __restrict__ faces,
                   const float* __restrict__ textures,
                   float* __restrict__ out) {
    __shared__ float4 s_c0[FF];          // {A0,B0,C0,A1}
    __shared__ float4 s_c1[FF];          // {B1,C1,iz0,iz1}
    __shared__ float  s_iz2[FF];
    __shared__ float4 s_tex[MAXT * 6];   // 9 KB
    __shared__ int    s_list[FF];
    __shared__ int    s_cnt[NWARPS];
    __shared__ float  s_rinvd[NPIX];
    __shared__ int    s_ridx[NPIX];

    const int tid  = (threadIdx.z * TILEY + threadIdx.y) * TILEX + threadIdx.x;
    const int warp = tid >> 5;
    const int lane = tid & 31;
    const int b = blockIdx.z;

    // Tile bounds in NDC (pixel-center extremes)
    const int ix0 = blockIdx.x * TILEX;
    const int iy0 = blockIdx.y * TILEY;
    const float pxmin = (2.0f * (ix0 + 0.5f) - WW) / WW;
    const float pxmax = (2.0f * (ix0 + TILEX - 1 + 0.5f) - WW) / WW;
    const float pymin = (2.0f * (iy0 + 0.5f) - HH) / HH;
    const float pymax = (2.0f * (iy0 + TILEY - 1 + 0.5f) - HH) / HH;

    // --- Phase 0: each thread owns faces fA = warp*64+lane, fB = fA+32.
    // Compute ONLY the bbox/validity predicate (cheap part).
    const int fA = warp * 64 + lane;
    const int fB = fA + 32;

    float ax0, ay0, az0, ax1, ay1, az1, ax2, ay2, az2, adet;
    float bx0, by0, bz0, bx1, by1, bz1, bx2, by2, bz2, bdet;
    bool pA, pB;
    {
        const float* f = faces + ((size_t)b * FF + fA) * 9;
        ax0 = f[0]; ay0 = f[1]; az0 = f[2];
        ax1 = f[3]; ay1 = f[4]; az1 = f[5];
        ax2 = f[6]; ay2 = f[7]; az2 = f[8];
        adet = (ax1 - ax0) * (ay2 - ay0) - (ax2 - ax0) * (ay1 - ay0);
        bool ok = fabsf(adet) > 1e-8f;
        float xmin = fminf(ax0, fminf(ax1, ax2)), xmax = fmaxf(ax0, fmaxf(ax1, ax2));
        float ymin = fminf(ay0, fminf(ay1, ay2)), ymax = fmaxf(ay0, fmaxf(ay1, ay2));
        pA = ok && (xmin <= pxmax) && (xmax >= pxmin) && (ymin <= pymax) && (ymax >= pymin);
    }
    {
        const float* f = faces + ((size_t)b * FF + fB) * 9;
        bx0 = f[0]; by0 = f[1]; bz0 = f[2];
        bx1 = f[3]; by1 = f[4]; bz1 = f[5];
        bx2 = f[6]; by2 = f[7]; bz2 = f[8];
        bdet = (bx1 - bx0) * (by2 - by0) - (bx2 - bx0) * (by1 - by0);
        bool ok = fabsf(bdet) > 1e-8f;
        float xmin = fminf(bx0, fminf(bx1, bx2)), xmax = fmaxf(bx0, fmaxf(bx1, bx2));
        float ymin = fminf(by0, fminf(by1, by2)), ymax = fmaxf(by0, fmaxf(by1, by2));
        pB = ok && (xmin <= pxmax) && (xmax >= pxmin) && (ymin <= pymax) && (ymax >= pymin);
    }

    // --- Phase 1: order-preserving warp compaction; SURVIVORS ONLY compute coefs.
    unsigned ball0 = __ballot_sync(0xffffffffu, pA);
    unsigned ball1 = __ballot_sync(0xffffffffu, pB);
    if (lane == 0) s_cnt[warp] = __popc(ball0) + __popc(ball1);
    __syncthreads();

    int offset = 0, total = 0;
    #pragma unroll
    for (int w = 0; w < NWARPS; w++) {
        int c = s_cnt[w];
        if (w < warp) offset += c;
        total += c;
    }

    {
        unsigned lt = (1u << lane) - 1u;
        if (pA) {
            int s = offset + __popc(ball0 & lt);
            float inv_det = 1.0f / adet;
            s_list[s] = fA;
            s_c0[s] = make_float4((ax1 * ay2 - ax2 * ay1) * inv_det,
                                  (ay1 - ay2) * inv_det,
                                  (ax2 - ax1) * inv_det,
                                  (ax2 * ay0 - ax0 * ay2) * inv_det);
            s_c1[s] = make_float4((ay2 - ay0) * inv_det,
                                  (ax0 - ax2) * inv_det,
                                  1.0f / az0, 1.0f / az1);
            s_iz2[s] = 1.0f / az2;
        }
        if (pB) {
            int s = offset + __popc(ball0) + __popc(ball1 & lt);
            float inv_det = 1.0f / bdet;
            s_list[s] = fB;
            s_c0[s] = make_float4((bx1 * by2 - bx2 * by1) * inv_det,
                                  (by1 - by2) * inv_det,
                                  (bx2 - bx1) * inv_det,
                                  (bx2 * by0 - bx0 * by2) * inv_det);
            s_c1[s] = make_float4((by2 - by0) * inv_det,
                                  (bx0 - bx2) * inv_det,
                                  1.0f / bz0, 1.0f / bz1);
            s_iz2[s] = 1.0f / bz2;
        }
    }
    __syncthreads();

    // --- Phase 2: issue async texture staging for survivors; completion is
    // awaited only after the z-loop (overlapped).
    {
        int ntex = (total < MAXT ? total : MAXT) * 6;
        const float4* txg = (const float4*)(textures + (size_t)b * FF * 3 * TT);
        for (int i = tid; i < ntex; i += NTHREADS) {
            int s = i / 6, part = i - s * 6;
            int f = s_list[s];
            cp_async16(&s_tex[i], &txg[f * 6 + part]);
        }
        asm volatile("cp.async.commit_group;\n" ::: "memory");
    }

    // --- Phase 3: per-pixel z-test; the two threadIdx.z halves split the list.
    const int ix = ix0 + threadIdx.x;
    const int iy = iy0 + threadIdx.y;
    const float px = (2.0f * (ix + 0.5f) - WW) / WW;
    const float py = (2.0f * (iy + 0.5f) - HH) / HH;

    const int half = (total + 1) >> 1;
    const int iBeg = threadIdx.z ? half : 0;
    const int iEnd = threadIdx.z ? total : half;

    float best_invd = 0.01f;  // 1/FAR: must strictly beat (depth < FAR)
    int best = -1;
    #pragma unroll 2
    for (int i = iBeg; i < iEnd; i++) {
        float4 c0 = s_c0[i];
        float4 c1 = s_c1[i];
        float iz2 = s_iz2[i];
        float w0 = fmaf(c0.z, py, fmaf(c0.y, px, c0.x));
        float w1 = fmaf(c1.y, py, fmaf(c1.x, px, c0.w));
        float w2 = 1.0f - w0 - w1;
        float invd = fmaf(w2, iz2, fmaf(w1, c1.w, w0 * c1.z));
        bool inside = (w0 >= 0.0f) && (w1 >= 0.0f) && (w2 >= 0.0f);
        if (inside && invd > best_invd && invd <= 2.0f) {  // 2.0 = 1/NEAR
            best_invd = invd;
            best = i;
        }
    }

    // --- Reduce the two halves; await texture staging.
    asm volatile("cp.async.wait_group 0;\n" ::: "memory");
    const int pidx = threadIdx.y * TILEX + threadIdx.x;
    if (threadIdx.z) {
        s_rinvd[pidx] = best_invd;
        s_ridx[pidx]  = best;
    }
    __syncthreads();
    if (threadIdx.z) return;

    {
        float oi = s_rinvd[pidx];
        // strict >: on ties the low half (earlier list index) wins -> argmin-first
        if (oi > best_invd) { best_invd = oi; best = s_ridx[pidx]; }
    }

    // --- Epilogue: texture interpolation + coalesced writes (32-wide rows).
    const int pix = iy * WW + ix;
    float* feature = out;                      // (B, 9, H, W)
    float* fim  = out + (size_t)BB * 9 * HW;   // (B, H, W) as float
    float* dmap = fim + (size_t)BB * HW;       // (B, H, W)
    float* fptr = feature + (size_t)b * 9 * HW + pix;

    if (best >= 0) {
        float4 c0 = s_c0[best];
        float4 c1 = s_c1[best];
        float w0 = fmaf(c0.z, py, fmaf(c0.y, px, c0.x));
        float w1 = fmaf(c1.y, py, fmaf(c1.x, px, c0.w));
        float w2 = 1.0f - w0 - w1;
        int f = s_list[best];
        float4 t0a, t0b, t1a, t1b, t2a, t2b;
        if (best < MAXT) {
            t0a = s_tex[best * 6 + 0]; t0b = s_tex[best * 6 + 1];
            t1a = s_tex[best * 6 + 2]; t1b = s_tex[best * 6 + 3];
            t2a = s_tex[best * 6 + 4]; t2b = s_tex[best * 6 + 5];
        } else {
            const float4* tx = (const float4*)(textures + ((size_t)(b * FF + f) * 3) * TT);
            t0a = tx[0]; t0b = tx[1]; t1a = tx[2]; t1b = tx[3]; t2a = tx[4]; t2b = tx[5];
        }
        float r[8];
        r[0] = w0 * t0a.x + w1 * t1a.x + w2 * t2a.x;
        r[1] = w0 * t0a.y + w1 * t1a.y + w2 * t2a.y;
        r[2] = w0 * t0a.z + w1 * t1a.z + w2 * t2a.z;
        r[3] = w0 * t0a.w + w1 * t1a.w + w2 * t2a.w;
        r[4] = w0 * t0b.x + w1 * t1b.x + w2 * t2b.x;
        r[5] = w0 * t0b.y + w1 * t1b.y + w2 * t2b.y;
        r[6] = w0 * t0b.z + w1 * t1b.z + w2 * t2b.z;
        r[7] = w0 * t0b.w + w1 * t1b.w + w2 * t2b.w;
        #pragma unroll
        for (int t = 0; t < 8; t++) fptr[(size_t)t * HW] = r[t];
        fptr[(size_t)8 * HW] = 1.0f;
        fim[(size_t)b * HW + pix]  = (float)f;
        dmap[(size_t)b * HW + pix] = 1.0f / best_invd;
    } else {
        #pragma unroll
        for (int t = 0; t < 8; t++) fptr[(size_t)t * HW] = 0.0f;
        fptr[(size_t)8 * HW] = 0.0f;
        fim[(size_t)b * HW + pix]  = -1.0f;
        dmap[(size_t)b * HW + pix] = 100.0f;  // FAR
    }
}

extern "C" void kernel_launch(void* const* d_in, const int* in_sizes, int n_in,
                              void* d_out, int out_size) {
    const float* faces    = (const float*)d_in[0];    // (B, F, 3, 3)
    const float* textures = (const float*)d_in[1];    // (B, F, 3, T)
    float* out = (float*)d_out;

    dim3 blk(TILEX, TILEY, 2);
    dim3 grd(WW / TILEX, HH / TILEY, BB);
    raster_kernel<<<grd, blk>>>(faces, textures, out);
}

// round 8
// speedup vs baseline: 1.0331x; 1.0331x over previous
#include <cuda_runtime.h>

// Problem constants
#define BB 2
#define FF 512
#define HH 192
#define WW 192
#define TT 8
#define HW (HH * WW)

#define TILEX 32
#define TILEY 16
#define NTHREADS 512
#define NWARPS 16
#define NPAIR (TILEX * 8)      // 256 pixel-pairs per block
#define MAXT 96                // texture staging capacity (typical survivors ~31)

__device__ __forceinline__ void cp_async16(void* dst_smem, const void* src_gmem) {
    unsigned saddr = (unsigned)__cvta_generic_to_shared(dst_smem);
    asm volatile("cp.async.cg.shared.global [%0], [%1], 16;\n"
                 :: "r"(saddr), "l"(src_gmem) : "memory");
}

__global__ __launch_bounds__(NTHREADS)
void raster_kernel(const float* __restrict__ faces,
                   const float* __restrict__ textures,
                   float* __restrict__ out) {
    __shared__ float4 s_c0[FF];           // {A0,B0,C0,A1}
    __shared__ float4 s_c1[FF];           // {B1,C1,iz0,iz1}
    __shared__ float  s_iz2[FF];
    __shared__ float4 s_tex[MAXT * 6];    // 9 KB
    __shared__ int    s_list[FF];
    __shared__ int    s_cnt[NWARPS];
    __shared__ float  s_rinvdA[NPAIR], s_rinvdB[NPAIR];
    __shared__ int    s_ridxA[NPAIR],  s_ridxB[NPAIR];

    const int tid  = (threadIdx.z * 8 + threadIdx.y) * TILEX + threadIdx.x;
    const int warp = tid >> 5;
    const int lane = tid & 31;
    const int b = blockIdx.z;

    // Tile bounds in NDC (pixel-center extremes)
    const int ix0 = blockIdx.x * TILEX;
    const int iy0 = blockIdx.y * TILEY;
    const float pxmin = (2.0f * (ix0 + 0.5f) - WW) / WW;
    const float pxmax = (2.0f * (ix0 + TILEX - 1 + 0.5f) - WW) / WW;
    const float pymin = (2.0f * (iy0 + 0.5f) - HH) / HH;
    const float pymax = (2.0f * (iy0 + TILEY - 1 + 0.5f) - HH) / HH;

    // --- Phase 0: each thread tests exactly ONE face (512 threads, 512 faces).
    float x0, y0, z0, x1, y1, z1, x2, y2, z2, det;
    bool p;
    {
        const float* f = faces + ((size_t)b * FF + tid) * 9;
        x0 = f[0]; y0 = f[1]; z0 = f[2];
        x1 = f[3]; y1 = f[4]; z1 = f[5];
        x2 = f[6]; y2 = f[7]; z2 = f[8];
        det = (x1 - x0) * (y2 - y0) - (x2 - x0) * (y1 - y0);
        bool ok = fabsf(det) > 1e-8f;
        float xmin = fminf(x0, fminf(x1, x2)), xmax = fmaxf(x0, fmaxf(x1, x2));
        float ymin = fminf(y0, fminf(y1, y2)), ymax = fmaxf(y0, fmaxf(y1, y2));
        p = ok && (xmin <= pxmax) && (xmax >= pxmin) && (ymin <= pymax) && (ymax >= pymin);
    }

    // --- Phase 1: order-preserving warp compaction; survivors compute coefs.
    unsigned ball = __ballot_sync(0xffffffffu, p);
    if (lane == 0) s_cnt[warp] = __popc(ball);
    __syncthreads();

    int offset = 0, total = 0;
    #pragma unroll
    for (int w = 0; w < NWARPS; w++) {
        int c = s_cnt[w];
        if (w < warp) offset += c;
        total += c;
    }

    if (p) {
        int s = offset + __popc(ball & ((1u << lane) - 1u));
        float inv_det = 1.0f / det;
        s_list[s] = tid;
        s_c0[s] = make_float4((x1 * y2 - x2 * y1) * inv_det,
                              (y1 - y2) * inv_det,
                              (x2 - x1) * inv_det,
                              (x2 * y0 - x0 * y2) * inv_det);
        s_c1[s] = make_float4((y2 - y0) * inv_det,
                              (x0 - x2) * inv_det,
                              1.0f / z0, 1.0f / z1);
        s_iz2[s] = 1.0f / z2;
    }
    __syncthreads();

    // --- Phase 2: async texture staging for survivors (awaited after z-loop).
    {
        int ntex = (total < MAXT ? total : MAXT) * 6;
        const float4* txg = (const float4*)(textures + (size_t)b * FF * 3 * TT);
        for (int i = tid; i < ntex; i += NTHREADS) {
            int s = i / 6, part = i - s * 6;
            cp_async16(&s_tex[i], &txg[s_list[s] * 6 + part]);
        }
        asm volatile("cp.async.commit_group;\n" ::: "memory");
    }

    // --- Phase 3: z-test. Each thread: 2 pixels (rows y, y+8), half the list.
    const int ix  = ix0 + threadIdx.x;
    const int iyA = iy0 + threadIdx.y;
    const int iyB = iyA + 8;
    const float px  = (2.0f * (ix + 0.5f) - WW) / WW;
    const float pyA = (2.0f * (iyA + 0.5f) - HH) / HH;
    const float pyB = (2.0f * (iyB + 0.5f) - HH) / HH;

    const int half = (total + 1) >> 1;
    const int iBeg = threadIdx.z ? half : 0;
    const int iEnd = threadIdx.z ? total : half;

    float bestA = 0.01f, bestB = 0.01f;   // 1/FAR sentinel
    int idxA = -1, idxB = -1;
    for (int i = iBeg; i < iEnd; i++) {
        float4 c0 = s_c0[i];
        float4 c1 = s_c1[i];
        float iz2 = s_iz2[i];
        float base0 = fmaf(c0.y, px, c0.x);
        float base1 = fmaf(c1.x, px, c0.w);
        // pixel A
        {
            float w0 = fmaf(c0.z, pyA, base0);
            float w1 = fmaf(c1.y, pyA, base1);
            float w2 = 1.0f - w0 - w1;
            float invd = fmaf(w2, iz2, fmaf(w1, c1.w, w0 * c1.z));
            bool hit = (w0 >= 0.0f) && (w1 >= 0.0f) && (w2 >= 0.0f) && (invd > bestA);
            if (hit) { bestA = invd; idxA = i; }
        }
        // pixel B
        {
            float w0 = fmaf(c0.z, pyB, base0);
            float w1 = fmaf(c1.y, pyB, base1);
            float w2 = 1.0f - w0 - w1;
            float invd = fmaf(w2, iz2, fmaf(w1, c1.w, w0 * c1.z));
            bool hit = (w0 >= 0.0f) && (w1 >= 0.0f) && (w2 >= 0.0f) && (invd > bestB);
            if (hit) { bestB = invd; idxB = i; }
        }
    }

    // --- Reduce halves; await texture staging.
    asm volatile("cp.async.wait_group 0;\n" ::: "memory");
    const int pidx = threadIdx.y * TILEX + threadIdx.x;
    if (threadIdx.z) {
        s_rinvdA[pidx] = bestA; s_ridxA[pidx] = idxA;
        s_rinvdB[pidx] = bestB; s_ridxB[pidx] = idxB;
    }
    __syncthreads();
    if (threadIdx.z) return;

    {
        float oa = s_rinvdA[pidx];
        if (oa > bestA) { bestA = oa; idxA = s_ridxA[pidx]; }  // strict >: earlier index wins ties
        float ob = s_rinvdB[pidx];
        if (ob > bestB) { bestB = ob; idxB = s_ridxB[pidx]; }
    }

    // --- Epilogue: interpolate + coalesced writes for both pixels.
    float* feature = out;                      // (B, 9, H, W)
    float* fim  = out + (size_t)BB * 9 * HW;   // (B, H, W) as float
    float* dmap = fim + (size_t)BB * HW;       // (B, H, W)

    #pragma unroll
    for (int pp = 0; pp < 2; pp++) {
        const int   best = pp ? idxB : idxA;
        const float binv = pp ? bestB : bestA;
        const float py   = pp ? pyB : pyA;
        const int   iy   = pp ? iyB : iyA;
        const int   pix  = iy * WW + ix;
        float* fptr = feature + (size_t)b * 9 * HW + pix;

        if (best >= 0) {
            float4 c0 = s_c0[best];
            float4 c1 = s_c1[best];
            float w0 = fmaf(c0.z, py, fmaf(c0.y, px, c0.x));
            float w1 = fmaf(c1.y, py, fmaf(c1.x, px, c0.w));
            float w2 = 1.0f - w0 - w1;
            int f = s_list[best];
            float4 t0a, t0b, t1a, t1b, t2a, t2b;
            if (best < MAXT) {
                t0a = s_tex[best * 6 + 0]; t0b = s_tex[best * 6 + 1];
                t1a = s_tex[best * 6 + 2]; t1b = s_tex[best * 6 + 3];
                t2a = s_tex[best * 6 + 4]; t2b = s_tex[best * 6 + 5];
            } else {
                const float4* tx = (const float4*)(textures + ((size_t)(b * FF + f) * 3) * TT);
                t0a = tx[0]; t0b = tx[1]; t1a = tx[2]; t1b = tx[3]; t2a = tx[4]; t2b = tx[5];
            }
            float r[8];
            r[0] = w0 * t0a.x + w1 * t1a.x + w2 * t2a.x;
            r[1] = w0 * t0a.y + w1 * t1a.y + w2 * t2a.y;
            r[2] = w0 * t0a.z + w1 * t1a.z + w2 * t2a.z;
            r[3] = w0 * t0a.w + w1 * t1a.w + w2 * t2a.w;
            r[4] = w0 * t0b.x + w1 * t1b.x + w2 * t2b.x;
            r[5] = w0 * t0b.y + w1 * t1b.y + w2 * t2b.y;
            r[6] = w0 * t0b.z + w1 * t1b.z + w2 * t2b.z;
            r[7] = w0 * t0b.w + w1 * t1b.w + w2 * t2b.w;
            #pragma unroll
            for (int t = 0; t < 8; t++) fptr[(size_t)t * HW] = r[t];
            fptr[(size_t)8 * HW] = 1.0f;
            fim[(size_t)b * HW + pix]  = (float)f;
            dmap[(size_t)b * HW + pix] = 1.0f / binv;
        } else {
            #pragma unroll
            for (int t = 0; t < 8; t++) fptr[(size_t)t * HW] = 0.0f;
            fptr[(size_t)8 * HW] = 0.0f;
            fim[(size_t)b * HW + pix]  = -1.0f;
            dmap[(size_t)b * HW + pix] = 100.0f;  // FAR
        }
    }
}

extern "C" void kernel_launch(void* const* d_in, const int* in_sizes, int n_in,
                              void* d_out, int out_size) {
    const float* faces    = (const float*)d_in[0];    // (B, F, 3, 3)
    const float* textures = (const float*)d_in[1];    // (B, F, 3, T)
    float* out = (float*)d_out;

    dim3 blk(TILEX, 8, 2);
    dim3 grd(WW / TILEX, HH / TILEY, BB);
    raster_kernel<<<grd, blk>>>(faces, textures, out);
}